// round 6
// baseline (speedup 1.0000x reference)
#include <cuda_runtime.h>
#include <cuda_bf16.h>
#include <cstdint>
#include <cstddef>

// Problem constants
// inputs: (32, 64, 64, 64) f32 ; emb_weight: (512, 64) f32
// Outputs concatenated as f32: loss(1) | quantized(32*64*64*64) | encoding_indices(131072) | perplexity(1) | codes(131072)
#define NB   32
#define NC   64
#define NHW  4096              // 64*64
#define NROW 131072            // NB*NHW
#define NK   512

#define OFF_LOSS  0
#define OFF_Q     1
#define OFF_IDX   8388609      // 1 + 32*64*64*64
#define OFF_PERP  8519681      // OFF_IDX + 131072
#define OFF_CODES 8519682

typedef unsigned long long ULL;

// ---------------------------------------------------------------------------
// f32x2 packed-math helpers (Blackwell sm_100+; ptxas never auto-fuses these)
// ---------------------------------------------------------------------------
__device__ __forceinline__ ULL f32x2_fma(ULL a, ULL b, ULL c) {
    ULL d;
    asm("fma.rn.f32x2 %0, %1, %2, %3;" : "=l"(d) : "l"(a), "l"(b), "l"(c));
    return d;
}
__device__ __forceinline__ ULL f32x2_bcast(float v) {
    ULL r;
    asm("mov.b64 %0, {%1, %2};" : "=l"(r) : "f"(v), "f"(v));
    return r;
}
__device__ __forceinline__ float2 f32x2_unpack(ULL v) {
    float2 r;
    asm("mov.b64 {%0, %1}, %2;" : "=f"(r.x), "=f"(r.y) : "l"(v));
    return r;
}

// ---------------------------------------------------------------------------
// Scratch (no allocations allowed -> __device__ globals)
// ---------------------------------------------------------------------------
__device__ int   g_idx[NROW];
__device__ float g_counts[NK];
__device__ float g_hn[NK];        // 0.5 * ||e_k||^2
__device__ float g_lossb[1024];   // per-block loss partial sums (deterministic)

// ---------------------------------------------------------------------------
// Kernel 0: init — half-norms of codes, zero histogram
// ---------------------------------------------------------------------------
__global__ void vq_init(const float* __restrict__ emb) {
    int t = threadIdx.x;               // 512 threads
    const float4* e = (const float4*)(emb + t * NC);
    float s = 0.f;
#pragma unroll
    for (int i = 0; i < 16; i++) {
        float4 v = e[i];
        s += v.x * v.x + v.y * v.y + v.z * v.z + v.w * v.w;
    }
    g_hn[t] = 0.5f * s;
    g_counts[t] = 0.f;
}

// ---------------------------------------------------------------------------
// Kernel 1: argmin GEMM. Block = 128 rows, 256 threads.
// Thread tile: 8 rows x 8 codes, rows accumulated pairwise via fma.rn.f32x2.
// Code tiles of 128 (4 tiles cover K=512). C=64 is the full reduction dim.
// ---------------------------------------------------------------------------
__global__ void __launch_bounds__(256, 1)
vq_argmin(const float* __restrict__ x_in, const float* __restrict__ emb) {
    extern __shared__ float sm[];
    float (*xs)[128] = (float (*)[128])sm;                 // [64][128] = 32 KB
    float (*es)[132] = (float (*)[132])(sm + 64 * 128);    // [64][132] = 33 KB (padded)
    float* hn_s = sm + 64 * 128 + 64 * 132;                // [128]
    float* red  = hn_s;                                    // reused after epilogue
    float* rvs  = (float*)es;                              // overlay: 16*128 floats
    int*   ris  = ((int*)es) + 16 * 128;                   // overlay: 16*128 ints

    const int tid = threadIdx.x;
    const int rg  = tid & 15;          // row group 0..15 (8 rows: pairs {2rg+32j, +1})
    const int cg  = tid >> 4;          // code group 0..15 (8 codes)
    const int n0  = blockIdx.x * 128;
    const int b   = n0 >> 12;
    const int hw0 = n0 & 4095;

    // Load x tile transposed: xs[c][m] = inputs[b][c][hw0+m]  (coalesced)
    const float* xbase = x_in + (size_t)b * (NC * NHW) + hw0;
    for (int i = tid; i < 64 * 128; i += 256) {
        int c = i >> 7, m = i & 127;
        xs[c][m] = xbase[(size_t)c * NHW + m];
    }

    float bestv[8];
    int   besti[8];
#pragma unroll
    for (int j = 0; j < 8; j++) { bestv[j] = -3.4e38f; besti[j] = 0; }

    for (int ct = 0; ct < 4; ct++) {
        __syncthreads();  // protect es/hn_s from previous tile's readers
        // Load 128-code tile transposed: es[c][code]
        const float* ebase = emb + (size_t)ct * 128 * NC;
        for (int i = tid; i < 128 * 64; i += 256) {
            es[i & 63][i >> 6] = ebase[i];
        }
        if (tid < 128) hn_s[tid] = g_hn[ct * 128 + tid];
        __syncthreads();

        ULL acc[4][8];
#pragma unroll
        for (int j = 0; j < 4; j++)
#pragma unroll
            for (int c = 0; c < 8; c++) acc[j][c] = 0ull;

#pragma unroll 8
        for (int k = 0; k < 64; k++) {
            ULL xv[4];
#pragma unroll
            for (int j = 0; j < 4; j++)
                xv[j] = *(const ULL*)&xs[k][2 * rg + 32 * j];   // (row, row+1) pair
            float4 ea = *(const float4*)&es[k][cg * 8];
            float4 eb = *(const float4*)&es[k][cg * 8 + 4];
            ULL ep[8];
            ep[0] = f32x2_bcast(ea.x); ep[1] = f32x2_bcast(ea.y);
            ep[2] = f32x2_bcast(ea.z); ep[3] = f32x2_bcast(ea.w);
            ep[4] = f32x2_bcast(eb.x); ep[5] = f32x2_bcast(eb.y);
            ep[6] = f32x2_bcast(eb.z); ep[7] = f32x2_bcast(eb.w);
#pragma unroll
            for (int j = 0; j < 4; j++)
#pragma unroll
                for (int c = 0; c < 8; c++)
                    acc[j][c] = f32x2_fma(xv[j], ep[c], acc[j][c]);
        }

        // Per-tile epilogue: score = dot - 0.5||e||^2 ; running argmax
        // (ascending code order -> first-min tie semantics preserved per thread)
#pragma unroll
        for (int c = 0; c < 8; c++) {
            float h = hn_s[cg * 8 + c];
            int code = ct * 128 + cg * 8 + c;
#pragma unroll
            for (int j = 0; j < 4; j++) {
                float2 a = f32x2_unpack(acc[j][c]);
                float s0 = a.x - h, s1 = a.y - h;
                if (s0 > bestv[2 * j])     { bestv[2 * j]     = s0; besti[2 * j]     = code; }
                if (s1 > bestv[2 * j + 1]) { bestv[2 * j + 1] = s1; besti[2 * j + 1] = code; }
            }
        }
    }

    __syncthreads();  // all done reading es -> safe to overlay reduce arrays
#pragma unroll
    for (int j = 0; j < 4; j++) {
#pragma unroll
        for (int p = 0; p < 2; p++) {
            int row = 2 * rg + 32 * j + p;
            rvs[cg * 128 + row] = bestv[2 * j + p];
            ris[cg * 128 + row] = besti[2 * j + p];
        }
    }
    __syncthreads();

    if (tid < 128) {
        int row = tid;
        float bv = rvs[row];
        int   bi = ris[row];
#pragma unroll
        for (int g = 1; g < 16; g++) {
            float v = rvs[g * 128 + row];
            if (v > bv) { bv = v; bi = ris[g * 128 + row]; }
        }
        // ||x||^2 for this row (xs intact)
        float xn = 0.f;
#pragma unroll
        for (int k = 0; k < 64; k++) { float xv = xs[k][row]; xn += xv * xv; }
        float d = xn - 2.f * bv;       // = ||x - e_best||^2
        int n = n0 + row;
        g_idx[n] = bi;
        atomicAdd(&g_counts[bi], 1.0f);   // integer-valued float adds: exact
        red[tid] = d;
    }
    __syncthreads();
#pragma unroll
    for (int o = 64; o >= 1; o >>= 1) {
        if (tid < o) red[tid] += red[tid + o];
        __syncthreads();
    }
    if (tid == 0) g_lossb[blockIdx.x] = red[0];
}

// ---------------------------------------------------------------------------
// Kernel 2: gather quantized output (NCHW) + write both index outputs.
// Full codebook staged in smem padded to 65 floats/row (bank-conflict fix).
// ---------------------------------------------------------------------------
__global__ void __launch_bounds__(256, 1)
vq_gather(const float* __restrict__ emb, float* __restrict__ out) {
    extern __shared__ float cb[];      // 512 * 65 floats
    int t = threadIdx.x;
    for (int i = t; i < NK * NC; i += 256)
        cb[(i >> 6) * 65 + (i & 63)] = emb[i];

    int n = blockIdx.x * 256 + t;      // 512 blocks cover 131072 rows
    int idx = g_idx[n];
    __syncthreads();

    int b = n >> 12, hw = n & 4095;
    float* qb = out + OFF_Q + (size_t)b * (NC * NHW) + hw;
    const float* cr = cb + idx * 65;
#pragma unroll
    for (int c = 0; c < 64; c++)
        qb[(size_t)c * NHW] = cr[c];   // consecutive threads -> consecutive hw: coalesced

    float fidx = (float)idx;
    out[OFF_IDX + n]   = fidx;
    out[OFF_CODES + n] = fidx;
}

// ---------------------------------------------------------------------------
// Kernel 3: finalize loss + perplexity (fixed-order reductions: deterministic)
// ---------------------------------------------------------------------------
__global__ void vq_finalize(float* __restrict__ out) {
    __shared__ float sp[512];
    __shared__ float sl[512];
    int t = threadIdx.x;
    float p = g_counts[t] * (1.0f / (float)NROW);
    sp[t] = p * logf(p + 1e-10f);
    sl[t] = g_lossb[t] + g_lossb[t + 512];
    __syncthreads();
#pragma unroll
    for (int o = 256; o >= 1; o >>= 1) {
        if (t < o) { sp[t] += sp[t + o]; sl[t] += sl[t + o]; }
        __syncthreads();
    }
    if (t == 0) {
        out[OFF_PERP] = expf(-sp[0]);
        out[OFF_LOSS] = 0.25f * sl[0] * (1.0f / 8388608.0f);  // BETA * mean over N*C
    }
}

// ---------------------------------------------------------------------------
// Launch
// ---------------------------------------------------------------------------
extern "C" void kernel_launch(void* const* d_in, const int* in_sizes, int n_in,
                              void* d_out, int out_size) {
    const float* x = (const float*)d_in[0];
    const float* e = (const float*)d_in[1];
    // Defensive: identify operands by size (inputs=8388608, emb=32768)
    if (n_in >= 2 && in_sizes[0] == NK * NC) {
        const float* tmp = x; x = e; e = tmp;
    }
    float* out = (float*)d_out;

    const int SMEM1 = (64 * 128 + 64 * 132 + 128) * (int)sizeof(float);  // 67072 B
    const int SMEM2 = NK * 65 * (int)sizeof(float);                      // 133120 B
    cudaFuncSetAttribute(vq_argmin, cudaFuncAttributeMaxDynamicSharedMemorySize, SMEM1);
    cudaFuncSetAttribute(vq_gather, cudaFuncAttributeMaxDynamicSharedMemorySize, SMEM2);

    vq_init<<<1, 512>>>(e);
    vq_argmin<<<NROW / 128, 256, SMEM1>>>(x, e);
    vq_gather<<<NROW / 256, 256, SMEM2>>>(e, out);
    vq_finalize<<<1, 512>>>(out);
}